// round 9
// baseline (speedup 1.0000x reference)
#include <cuda_runtime.h>
#include <cuda_fp16.h>
#include <cstdint>

// BoltzmannRouter (round 8): legacy mma.sync fp16 2-way-split GEMM (fp32-grade)
// scores = x @ w^T via 4 split-product HMMAs per k16; fused softmax/top-44.
// x: [16384, 2048] f32, gate_w: [64, 2048] f32, out: [16384, 64] f32

#define D_DIM 2048
#define E_DIM 64
#define BT    128
#define KC    64
#define NC    (D_DIM / KC)     // 32
#define N_ACTIVE 44
#define SC_STRIDE 66

#define ROW_STRIDE 160         // bytes per smem row (80 halves; conflict-free LDS.64)
#define A_PLANE (128 * ROW_STRIDE)      // 20480
#define B_PLANE (64 * ROW_STRIDE)       // 10240
#define OFF_A 0
#define OFF_B (2 * A_PLANE)             // 40960
#define SMEM_TOTAL (OFF_B + 2 * B_PLANE) // 61440

static __device__ __forceinline__ void mma16816(float* d,
    uint32_t a0, uint32_t a1, uint32_t a2, uint32_t a3, uint32_t b0, uint32_t b1)
{
    asm volatile(
        "mma.sync.aligned.m16n8k16.row.col.f32.f16.f16.f32 "
        "{%0,%1,%2,%3}, {%4,%5,%6,%7}, {%8,%9}, {%0,%1,%2,%3};"
        : "+f"(d[0]), "+f"(d[1]), "+f"(d[2]), "+f"(d[3])
        : "r"(a0), "r"(a1), "r"(a2), "r"(a3), "r"(b0), "r"(b1));
}

// storage column of k' within a 16-k group: [0,1,8,9, 2,3,10,11, 4,5,12,13, 6,7,14,15]
// puts thread-(t) fragment halves {2t,2t+1,2t+8,2t+9} at 4 contiguous slots 4t..4t+3.
static __device__ __forceinline__ int scol(int kk) {
    return ((kk & 7) >> 1) * 4 + ((kk >> 3) << 1);
}

// exact fp16 2-way split of a float pair; store hi/lo planes
static __device__ __forceinline__ void split_store(
    char* sm, int base, int plane, int row, int col_halves, float v0, float v1)
{
    __half2 h = __floats2half2_rn(v0, v1);                 // low=v0, high=v1
    float r0 = v0 - __low2float(h);                        // exact
    float r1 = v1 - __high2float(h);
    __half2 l = __floats2half2_rn(r0, r1);
    char* p = sm + base + row * ROW_STRIDE + col_halves * 2;
    *reinterpret_cast<__half2*>(p)         = h;
    *reinterpret_cast<__half2*>(p + plane) = l;
}

__global__ __launch_bounds__(256, 1)
void boltzmann_router_mma(const float* __restrict__ x,
                          const float* __restrict__ w,
                          float* __restrict__ out)
{
    extern __shared__ __align__(16) char sm[];
    const int tid  = threadIdx.x;
    const int lane = tid & 31;
    const int warp = tid >> 5;            // 8 warps
    const int tok0 = blockIdx.x * BT;

    // GEMM mapping: warp = 2 m-tiles x 4 n-tiles (32 tokens x 32 experts)
    const int warp_m = warp >> 1;         // 0..3
    const int warp_n = warp & 1;          // 0..1
    const int tm = warp_m * 32;
    const int en = warp_n * 32;
    const int g = lane >> 2, t = lane & 3;

    float d[2][4][4];
    #pragma unroll
    for (int m = 0; m < 2; m++)
        #pragma unroll
        for (int n = 0; n < 4; n++)
            #pragma unroll
            for (int q = 0; q < 4; q++) d[m][n][q] = 0.0f;

    // loader coords
    const int xtok = tid >> 1, xkb = (tid & 1) * 32;   // token row, k base (32 floats)
    const int wexp = tid >> 2, wkb = (tid & 3) * 16;   // expert row, k base (16 floats)
    const float* xp = x + (size_t)(tok0 + xtok) * D_DIM + xkb;
    const float* wp = w + (size_t)wexp * D_DIM + wkb;

    float4 rx[8], rw[4];
    #pragma unroll
    for (int i = 0; i < 8; i++) rx[i] = *reinterpret_cast<const float4*>(xp + i * 4);
    #pragma unroll
    for (int i = 0; i < 4; i++) rw[i] = *reinterpret_cast<const float4*>(wp + i * 4);

    for (int c = 0; c < NC; c++) {
        // ---- convert held regs -> fp16 hi/lo planes (permuted k layout) ----
        #pragma unroll
        for (int i = 0; i < 8; i++) {
            int kl = xkb + i * 4;
            int c0 = ((kl >> 4) << 4) + scol(kl & 15);
            int c2 = (((kl + 2) >> 4) << 4) + scol((kl + 2) & 15);
            split_store(sm, OFF_A, A_PLANE, xtok, c0, rx[i].x, rx[i].y);
            split_store(sm, OFF_A, A_PLANE, xtok, c2, rx[i].z, rx[i].w);
        }
        #pragma unroll
        for (int i = 0; i < 4; i++) {
            int kl = wkb + i * 4;
            int c0 = ((kl >> 4) << 4) + scol(kl & 15);
            int c2 = (((kl + 2) >> 4) << 4) + scol((kl + 2) & 15);
            split_store(sm, OFF_B, B_PLANE, wexp, c0, rw[i].x, rw[i].y);
            split_store(sm, OFF_B, B_PLANE, wexp, c2, rw[i].z, rw[i].w);
        }
        __syncthreads();

        // ---- prefetch next chunk (overlaps MMA below) ----
        if (c + 1 < NC) {
            #pragma unroll
            for (int i = 0; i < 8; i++)
                rx[i] = *reinterpret_cast<const float4*>(xp + (c + 1) * KC + i * 4);
            #pragma unroll
            for (int i = 0; i < 4; i++)
                rw[i] = *reinterpret_cast<const float4*>(wp + (c + 1) * KC + i * 4);
        }

        // ---- 4 k16 steps of split-product MMAs ----
        #pragma unroll
        for (int ks = 0; ks < 4; ks++) {
            const int kcol = (ks * 16 + 4 * t) * 2;   // byte offset within row
            // A fragments: [mtile][split] = {a0,a1,a2,a3}
            uint4 af[2][2];
            #pragma unroll
            for (int m = 0; m < 2; m++)
                #pragma unroll
                for (int p = 0; p < 2; p++) {
                    const char* pa = sm + OFF_A + p * A_PLANE
                                   + (tm + m * 16 + g) * ROW_STRIDE + kcol;
                    uint2 lo = *reinterpret_cast<const uint2*>(pa);
                    uint2 hi = *reinterpret_cast<const uint2*>(pa + 8 * ROW_STRIDE);
                    af[m][p] = make_uint4(lo.x, hi.x, lo.y, hi.y);  // a0,a1,a2,a3
                }
            #pragma unroll
            for (int n = 0; n < 4; n++) {
                const char* pb = sm + OFF_B + (en + n * 8 + g) * ROW_STRIDE + kcol;
                uint2 bh = *reinterpret_cast<const uint2*>(pb);            // hi split
                uint2 bl = *reinterpret_cast<const uint2*>(pb + B_PLANE);  // lo split
                #pragma unroll
                for (int m = 0; m < 2; m++) {
                    mma16816(d[m][n], af[m][0].x, af[m][0].y, af[m][0].z, af[m][0].w, bh.x, bh.y);
                    mma16816(d[m][n], af[m][0].x, af[m][0].y, af[m][0].z, af[m][0].w, bl.x, bl.y);
                    mma16816(d[m][n], af[m][1].x, af[m][1].y, af[m][1].z, af[m][1].w, bh.x, bh.y);
                    mma16816(d[m][n], af[m][1].x, af[m][1].y, af[m][1].z, af[m][1].w, bl.x, bl.y);
                }
            }
        }
        __syncthreads();
    }

    // ---- write scaled scores to smem (aliases A planes) ----
    float* sc = reinterpret_cast<float*>(sm);
    const float INV_TEMP = 0.36787944117144233f;  // 1/e
    #pragma unroll
    for (int m = 0; m < 2; m++) {
        int r0 = tm + m * 16 + g, r1 = r0 + 8;
        #pragma unroll
        for (int n = 0; n < 4; n++) {
            int cb = en + n * 8 + 2 * t;
            sc[r0 * SC_STRIDE + cb]     = d[m][n][0] * INV_TEMP;
            sc[r0 * SC_STRIDE + cb + 1] = d[m][n][1] * INV_TEMP;
            sc[r1 * SC_STRIDE + cb]     = d[m][n][2] * INV_TEMP;
            sc[r1 * SC_STRIDE + cb + 1] = d[m][n][3] * INV_TEMP;
        }
    }
    __syncthreads();

    // ---- epilogue: one warp per 16 tokens (softmax + top-44 + renorm) ----
    for (int tt = 0; tt < 16; tt++) {
        int tk = warp * 16 + tt;
        float s0 = sc[tk * SC_STRIDE + lane];
        float s1 = sc[tk * SC_STRIDE + 32 + lane];

        float mx = fmaxf(s0, s1);
        #pragma unroll
        for (int o = 16; o > 0; o >>= 1)
            mx = fmaxf(mx, __shfl_xor_sync(0xFFFFFFFFu, mx, o));

        float e0v = __expf(s0 - mx);
        float e1v = __expf(s1 - mx);
        float z = e0v + e1v;
        #pragma unroll
        for (int o = 16; o > 0; o >>= 1)
            z += __shfl_xor_sync(0xFFFFFFFFu, z, o);

        // rank = #{j : s_j > s_i, ties broken by lower index}
        int c0 = 0, c1 = 0;
        #pragma unroll 16
        for (int j = 0; j < E_DIM; j++) {
            float sj = sc[tk * SC_STRIDE + j];
            c0 += (sj > s0) || (sj == s0 && j < lane);
            c1 += (sj > s1) || (sj == s1 && j < lane + 32);
        }
        bool keep0 = c0 < N_ACTIVE;
        bool keep1 = c1 < N_ACTIVE;

        float sk = (keep0 ? e0v : 0.0f) + (keep1 ? e1v : 0.0f);
        #pragma unroll
        for (int o = 16; o > 0; o >>= 1)
            sk += __shfl_xor_sync(0xFFFFFFFFu, sk, o);

        float inv = 1.0f / (sk + 1e-8f * z);
        size_t base = (size_t)(tok0 + tk) * E_DIM;
        out[base + lane]      = keep0 ? e0v * inv : 0.0f;
        out[base + lane + 32] = keep1 ? e1v * inv : 0.0f;
    }
}

extern "C" void kernel_launch(void* const* d_in, const int* in_sizes, int n_in,
                              void* d_out, int out_size)
{
    const float* x = (const float*)d_in[0];   // [N, 2048]
    const float* w = (const float*)d_in[1];   // [64, 2048]
    float* out     = (float*)d_out;           // [N, 64]
    int ntok = in_sizes[0] / D_DIM;           // 16384

    cudaFuncSetAttribute(boltzmann_router_mma,
                         cudaFuncAttributeMaxDynamicSharedMemorySize, SMEM_TOTAL);
    boltzmann_router_mma<<<ntok / BT, 256, SMEM_TOTAL>>>(x, w, out);
}